// round 2
// baseline (speedup 1.0000x reference)
#include <cuda_runtime.h>

#define N_NODES 50000
#define N_EDGES 800000
#define DIM     128
#define NGRAPH  64

// ---------------- scratch (static device globals; no allocation) ----------------
__device__ float g_bufA[N_NODES * DIM];
__device__ float g_bufB[N_NODES * DIM];
__device__ int   g_deg[N_NODES];
__device__ float g_dinv[N_NODES];
__device__ int   g_off[N_NODES + 1];
__device__ int   g_cur[N_NODES];
__device__ int   g_csrc[N_EDGES];
__device__ float g_cnrm[N_EDGES];
__device__ int   g_is64;   // 1 if index tensors are int64, 0 if int32

// ---------------- dtype detection ----------------
// If edge_index is int64 with values < 50000, every odd int32 word is 0.
// If int32, odd words are random node ids (all-zero over 256 samples ~ impossible).
__global__ void k_detect(const int* __restrict__ probe) {
    __shared__ int nz;
    if (threadIdx.x == 0) nz = 0;
    __syncthreads();
    if (probe[threadIdx.x * 2 + 1] != 0) atomicAdd(&nz, 1);
    __syncthreads();
    if (threadIdx.x == 0) g_is64 = (nz == 0) ? 1 : 0;
}

__device__ __forceinline__ int ldidx(const void* __restrict__ p, long long i) {
    if (g_is64) return (int)((const long long*)p)[i];
    return ((const int*)p)[i];
}

// ---------------- preprocessing ----------------
__global__ void k_init() {
    int i = blockIdx.x * blockDim.x + threadIdx.x;
    if (i < N_NODES) { g_deg[i] = 0; g_cur[i] = 0; }
}

__global__ void k_degree(const void* __restrict__ ei) {
    int e = blockIdx.x * blockDim.x + threadIdx.x;
    if (e < N_EDGES) atomicAdd(&g_deg[ldidx(ei, N_EDGES + e)], 1);
}

__global__ void k_dinv() {
    int i = blockIdx.x * blockDim.x + threadIdx.x;
    if (i < N_NODES) g_dinv[i] = rsqrtf((float)(g_deg[i] + 1));  // +1 self loop
}

__global__ void k_scan() {
    __shared__ int part[1024];
    const int CH = (N_NODES + 1023) / 1024;
    int t = threadIdx.x;
    int b = t * CH;
    int e = b + CH; if (e > N_NODES) e = N_NODES;
    int s = 0;
    for (int i = b; i < e; i++) s += g_deg[i];
    part[t] = s;
    __syncthreads();
    for (int d = 1; d < 1024; d <<= 1) {
        int v = (t >= d) ? part[t - d] : 0;
        __syncthreads();
        part[t] += v;
        __syncthreads();
    }
    int run = (t > 0) ? part[t - 1] : 0;
    for (int i = b; i < e; i++) { g_off[i] = run; run += g_deg[i]; }
    if (t == 1023) g_off[N_NODES] = part[1023];
}

__global__ void k_fill(const void* __restrict__ ei) {
    int e = blockIdx.x * blockDim.x + threadIdx.x;
    if (e >= N_EDGES) return;
    int s = ldidx(ei, e);
    int d = ldidx(ei, N_EDGES + e);
    int p = g_off[d] + atomicAdd(&g_cur[d], 1);
    g_csrc[p] = s;
    g_cnrm[p] = g_dinv[s] * g_dinv[d];
}

// ---------------- dense GEMM: C[N,128] = A[N,128] @ W[128,128] ----------------
#define BM  64
#define TK  32
#define HSS 36   // padded row stride for Hs

extern __shared__ float s_mem[];

__global__ void __launch_bounds__(256) k_gemm(const float* __restrict__ A,
                                              const float* __restrict__ W,
                                              float* __restrict__ C) {
    float* Ws = s_mem;                 // 128*128 floats (64 KB)
    float* Hs = s_mem + DIM * DIM;     // BM*HSS floats

    int tid = threadIdx.x;

    // load full W into smem (reused across all row tiles this block handles)
    const float4* W4 = (const float4*)W;
    float4* Ws4 = (float4*)Ws;
    for (int i = tid; i < DIM * DIM / 4; i += 256) Ws4[i] = W4[i];

    int tr = tid >> 4;        // 0..15 -> rows tr*4 .. tr*4+3
    int tc = tid & 15;        // 0..15 -> cols tc*8 .. tc*8+7
    int lm = tid >> 3;        // 0..31 for Hs loading
    int lk = (tid & 7) << 2;  // 0,4,...,28

    int ntiles = (N_NODES + BM - 1) / BM;
    for (int tile = blockIdx.x; tile < ntiles; tile += gridDim.x) {
        int m0 = tile * BM;
        float acc[4][8];
        #pragma unroll
        for (int i = 0; i < 4; i++)
            #pragma unroll
            for (int j = 0; j < 8; j++) acc[i][j] = 0.f;

        for (int kk = 0; kk < DIM; kk += TK) {
            __syncthreads();
            // stage A tile [BM x TK] into Hs
            for (int mm = lm; mm < BM; mm += 32) {
                int row = m0 + mm;
                float4 v = make_float4(0.f, 0.f, 0.f, 0.f);
                if (row < N_NODES)
                    v = *(const float4*)&A[(long long)row * DIM + kk + lk];
                *(float4*)&Hs[mm * HSS + lk] = v;
            }
            __syncthreads();

            #pragma unroll 4
            for (int k = 0; k < TK; k++) {
                float a[4];
                #pragma unroll
                for (int i = 0; i < 4; i++)
                    a[i] = Hs[(tr * 4 + i) * HSS + k];
                float4 b0 = *(const float4*)&Ws[(kk + k) * DIM + tc * 8];
                float4 b1 = *(const float4*)&Ws[(kk + k) * DIM + tc * 8 + 4];
                float b[8] = {b0.x, b0.y, b0.z, b0.w, b1.x, b1.y, b1.z, b1.w};
                #pragma unroll
                for (int i = 0; i < 4; i++)
                    #pragma unroll
                    for (int j = 0; j < 8; j++)
                        acc[i][j] += a[i] * b[j];
            }
        }

        #pragma unroll
        for (int i = 0; i < 4; i++) {
            int row = m0 + tr * 4 + i;
            if (row < N_NODES) {
                float4 o0 = make_float4(acc[i][0], acc[i][1], acc[i][2], acc[i][3]);
                float4 o1 = make_float4(acc[i][4], acc[i][5], acc[i][6], acc[i][7]);
                *(float4*)&C[(long long)row * DIM + tc * 8]     = o0;
                *(float4*)&C[(long long)row * DIM + tc * 8 + 4] = o1;
            }
        }
    }
}
#define GEMM_SMEM ((DIM * DIM + BM * HSS) * 4)

// ---------------- SpMM: out[i] = relu(sum_e nrm*hw[src] + dinv^2*hw[i] + b) ----------------
__device__ __forceinline__ float4 f4fma(float s, float4 v, float4 a) {
    a.x += s * v.x; a.y += s * v.y; a.z += s * v.z; a.w += s * v.w; return a;
}

__global__ void __launch_bounds__(256) k_spmm(const float* __restrict__ hw,
                                              const float* __restrict__ bias,
                                              float* __restrict__ hout) {
    int warp = (blockIdx.x * blockDim.x + threadIdx.x) >> 5;
    int lane = threadIdx.x & 31;
    if (warp >= N_NODES) return;
    int i = warp;

    const float4* hw4 = (const float4*)hw;
    float di = g_dinv[i];
    float4 acc = hw4[(long long)i * 32 + lane];
    float sl = di * di;
    acc.x *= sl; acc.y *= sl; acc.z *= sl; acc.w *= sl;

    int p = g_off[i], pe = g_off[i + 1];
    for (; p + 4 <= pe; p += 4) {
        int   s0 = g_csrc[p],     s1 = g_csrc[p + 1];
        int   s2 = g_csrc[p + 2], s3 = g_csrc[p + 3];
        float n0 = g_cnrm[p],     n1 = g_cnrm[p + 1];
        float n2 = g_cnrm[p + 2], n3 = g_cnrm[p + 3];
        float4 v0 = hw4[(long long)s0 * 32 + lane];
        float4 v1 = hw4[(long long)s1 * 32 + lane];
        float4 v2 = hw4[(long long)s2 * 32 + lane];
        float4 v3 = hw4[(long long)s3 * 32 + lane];
        acc = f4fma(n0, v0, acc);
        acc = f4fma(n1, v1, acc);
        acc = f4fma(n2, v2, acc);
        acc = f4fma(n3, v3, acc);
    }
    for (; p < pe; p++) {
        int s = g_csrc[p];
        acc = f4fma(g_cnrm[p], hw4[(long long)s * 32 + lane], acc);
    }

    float4 bv = ((const float4*)bias)[lane];
    acc.x = fmaxf(acc.x + bv.x, 0.f);
    acc.y = fmaxf(acc.y + bv.y, 0.f);
    acc.z = fmaxf(acc.z + bv.z, 0.f);
    acc.w = fmaxf(acc.w + bv.w, 0.f);
    ((float4*)hout)[(long long)i * 32 + lane] = acc;
}

// ---------------- global mean pool (batch is sorted) ----------------
__device__ __forceinline__ int lbound(const void* __restrict__ b, int key) {
    int lo = 0, hi = N_NODES;
    while (lo < hi) {
        int mid = (lo + hi) >> 1;
        if (ldidx(b, mid) < key) lo = mid + 1; else hi = mid;
    }
    return lo;
}

__global__ void k_zero_out(float* __restrict__ out) {
    int i = blockIdx.x * blockDim.x + threadIdx.x;
    if (i < NGRAPH * DIM) out[i] = 0.f;
}

#define PCH 16
__global__ void k_pool(const float* __restrict__ h,
                       const void* __restrict__ batch,
                       float* __restrict__ out) {
    int g = blockIdx.x / PCH;
    int c = blockIdx.x % PCH;
    int t = threadIdx.x;  // 0..127 (one column each)
    int start = lbound(batch, g);
    int end   = lbound(batch, g + 1);
    int len = end - start;
    int rs = start + (int)((long long)len * c / PCH);
    int re = start + (int)((long long)len * (c + 1) / PCH);
    float s = 0.f;
    for (int r = rs; r < re; r++) s += h[(long long)r * DIM + t];
    atomicAdd(&out[g * DIM + t], s);
}

__global__ void k_pool_div(const void* __restrict__ batch, float* __restrict__ out) {
    int g = blockIdx.x;
    int t = threadIdx.x;
    int start = lbound(batch, g);
    int end   = lbound(batch, g + 1);
    float cnt = (float)(end - start);
    if (cnt < 1.f) cnt = 1.f;
    out[g * DIM + t] /= cnt;
}

// ---------------- launch ----------------
extern "C" void kernel_launch(void* const* d_in, const int* in_sizes, int n_in,
                              void* d_out, int out_size) {
    (void)out_size;
    // Identify inputs by element count (robust to metadata ordering):
    //   x: 6,400,000   edge_index: 1,600,000   batch: 50,000
    //   W0/W1/W2: 16,384 (appearance order)   b0/b1/b2: 128 (appearance order)
    const float* x = 0; const void* ei = 0; const void* batch = 0;
    const float* W[3] = {0, 0, 0}; const float* b[3] = {0, 0, 0};
    int nw = 0, nb = 0;
    for (int i = 0; i < n_in; i++) {
        int sz = in_sizes[i];
        if      (sz == N_NODES * DIM) x     = (const float*)d_in[i];
        else if (sz == 2 * N_EDGES)   ei    = d_in[i];
        else if (sz == N_NODES)       batch = d_in[i];
        else if (sz == DIM * DIM)     { if (nw < 3) W[nw++] = (const float*)d_in[i]; }
        else if (sz == DIM)           { if (nb < 3) b[nb++] = (const float*)d_in[i]; }
    }
    float* out = (float*)d_out;

    cudaFuncSetAttribute(k_gemm, cudaFuncAttributeMaxDynamicSharedMemorySize, GEMM_SMEM);

    void *pA_, *pB_;
    cudaGetSymbolAddress(&pA_, g_bufA);
    cudaGetSymbolAddress(&pB_, g_bufB);
    float* A = (float*)pA_;
    float* B = (float*)pB_;

    const int NT = 256;
    int nblk = (N_NODES + NT - 1) / NT;
    int eblk = (N_EDGES + NT - 1) / NT;

    // dtype probe + preprocess: degrees, norm, CSR (rebuilt every call; deterministic)
    k_detect<<<1, 256>>>((const int*)ei);
    k_init<<<nblk, NT>>>();
    k_degree<<<eblk, NT>>>(ei);
    k_dinv<<<nblk, NT>>>();
    k_scan<<<1, 1024>>>();
    k_fill<<<eblk, NT>>>(ei);

    int spmm_blocks = (N_NODES * 32 + NT - 1) / NT;
    const int gemm_grid = 456;  // ~3 blocks/SM on 152 SMs

    // layer 1
    k_gemm<<<gemm_grid, 256, GEMM_SMEM>>>(x, W[0], A);
    k_spmm<<<spmm_blocks, NT>>>(A, b[0], B);
    // layer 2
    k_gemm<<<gemm_grid, 256, GEMM_SMEM>>>(B, W[1], A);
    k_spmm<<<spmm_blocks, NT>>>(A, b[1], B);
    // layer 3
    k_gemm<<<gemm_grid, 256, GEMM_SMEM>>>(B, W[2], A);
    k_spmm<<<spmm_blocks, NT>>>(A, b[2], B);

    // pool
    k_zero_out<<<(NGRAPH * DIM + NT - 1) / NT, NT>>>(out);
    k_pool<<<NGRAPH * PCH, DIM>>>(B, batch, out);
    k_pool_div<<<NGRAPH, DIM>>>(batch, out);
}

// round 4
// speedup vs baseline: 1.4995x; 1.4995x over previous
#include <cuda_runtime.h>
#include <cuda_bf16.h>
#include <cuda_fp16.h>
#include <cstdint>

#define N_NODES 50000
#define N_EDGES 800000
#define DIM     128
#define NGRAPH  64

// ---------------- scratch (static device globals; no allocation) ----------------
__device__ __nv_bfloat16 g_Ahi[N_NODES * DIM];   // GEMM input hi
__device__ __nv_bfloat16 g_Alo[N_NODES * DIM];   // GEMM input lo
__device__ float         g_hw [N_NODES * DIM];   // GEMM output (SpMM gather input)
__device__ __nv_bfloat16 g_Whi[DIM * DIM];       // W^T hi  [n][k]
__device__ __nv_bfloat16 g_Wlo[DIM * DIM];       // W^T lo  [n][k]
__device__ int   g_deg[N_NODES];
__device__ float g_dinv[N_NODES];
__device__ int   g_off[N_NODES + 1];
__device__ int   g_cur[N_NODES];
__device__ int   g_csrc[N_EDGES];
__device__ float g_cnrm[N_EDGES];
__device__ int   g_is64;

// ---------------- small helpers ----------------
__device__ __forceinline__ int ldidx(const void* __restrict__ p, long long i) {
    if (g_is64) return (int)((const long long*)p)[i];
    return ((const int*)p)[i];
}
__device__ __forceinline__ uint32_t smem_u32(const void* p) {
    uint32_t a;
    asm("{ .reg .u64 t; cvta.to.shared.u64 t, %1; cvt.u32.u64 %0, t; }" : "=r"(a) : "l"(p));
    return a;
}
__device__ __forceinline__ uint32_t packbf2(float a, float b) {
    __nv_bfloat162 t = __floats2bfloat162_rn(a, b);
    return *reinterpret_cast<uint32_t*>(&t);
}

// ---------------- dtype detection (int32 vs int64 indices) ----------------
__global__ void k_detect(const int* __restrict__ probe) {
    __shared__ int nz;
    if (threadIdx.x == 0) nz = 0;
    __syncthreads();
    if (probe[threadIdx.x * 2 + 1] != 0) atomicAdd(&nz, 1);
    __syncthreads();
    if (threadIdx.x == 0) g_is64 = (nz == 0) ? 1 : 0;
}

// ---------------- preprocessing: CSR by dst ----------------
__global__ void k_init() {
    int i = blockIdx.x * blockDim.x + threadIdx.x;
    if (i < N_NODES) { g_deg[i] = 0; g_cur[i] = 0; }
}
__global__ void k_degree(const void* __restrict__ ei) {
    int e = blockIdx.x * blockDim.x + threadIdx.x;
    if (e < N_EDGES) atomicAdd(&g_deg[ldidx(ei, N_EDGES + e)], 1);
}
__global__ void k_dinv() {
    int i = blockIdx.x * blockDim.x + threadIdx.x;
    if (i < N_NODES) g_dinv[i] = rsqrtf((float)(g_deg[i] + 1));
}
__global__ void k_scan() {
    __shared__ int part[1024];
    const int CH = (N_NODES + 1023) / 1024;
    int t = threadIdx.x;
    int b = t * CH;
    int e = b + CH; if (e > N_NODES) e = N_NODES;
    int s = 0;
    for (int i = b; i < e; i++) s += g_deg[i];
    part[t] = s;
    __syncthreads();
    for (int d = 1; d < 1024; d <<= 1) {
        int v = (t >= d) ? part[t - d] : 0;
        __syncthreads();
        part[t] += v;
        __syncthreads();
    }
    int run = (t > 0) ? part[t - 1] : 0;
    for (int i = b; i < e; i++) { g_off[i] = run; run += g_deg[i]; }
    if (t == 1023) g_off[N_NODES] = part[1023];
}
__global__ void k_fill(const void* __restrict__ ei) {
    int e = blockIdx.x * blockDim.x + threadIdx.x;
    if (e >= N_EDGES) return;
    int s = ldidx(ei, e);
    int d = ldidx(ei, N_EDGES + e);
    int p = g_off[d] + atomicAdd(&g_cur[d], 1);
    g_csrc[p] = s;
    g_cnrm[p] = g_dinv[s] * g_dinv[d];
}

// ---------------- input conversion ----------------
__global__ void k_splitX(const float* __restrict__ x) {
    int i = blockIdx.x * blockDim.x + threadIdx.x;   // one float4 per thread
    if (i >= N_NODES * DIM / 4) return;
    float4 v = ((const float4*)x)[i];
    uint2 ph, pl;
    ph.x = packbf2(v.x, v.y); ph.y = packbf2(v.z, v.w);
    __nv_bfloat162 t0 = *reinterpret_cast<__nv_bfloat162*>(&ph.x);
    __nv_bfloat162 t1 = *reinterpret_cast<__nv_bfloat162*>(&ph.y);
    pl.x = packbf2(v.x - __bfloat162float(t0.x), v.y - __bfloat162float(t0.y));
    pl.y = packbf2(v.z - __bfloat162float(t1.x), v.w - __bfloat162float(t1.y));
    ((uint2*)g_Ahi)[i] = ph;
    ((uint2*)g_Alo)[i] = pl;
}

// W [k][n] fp32 -> W^T [n][k] (hi, lo) bf16
__global__ void k_prepW(const float* __restrict__ W) {
    int idx = blockIdx.x * blockDim.x + threadIdx.x;
    if (idx >= DIM * DIM) return;
    int k = idx >> 7, n = idx & 127;
    float v = W[idx];
    __nv_bfloat16 hi = __float2bfloat16_rn(v);
    float lo = v - __bfloat162float(hi);
    g_Whi[n * DIM + k] = hi;
    g_Wlo[n * DIM + k] = __float2bfloat16_rn(lo);
}

// ---------------- mma.sync GEMM: g_hw[m][n] = sum_k A[m][k] * W[k][n] ----------------
// bf16 split x split (3 products), fp32 register accumulators, fp32 output.
// Block: 128 threads (4 warps), tile M=64, N=128, K=128.
#define SAS 272                 // smem row stride in BYTES (136 bf16)
#define SM_AH 0
#define SM_AL (SM_AH + 64 * SAS)
#define SM_WH (SM_AL + 64 * SAS)
#define SM_WL (SM_WH + 128 * SAS)
#define SM_TOT (SM_WL + 128 * SAS)

__device__ __forceinline__ void ldsm4(uint32_t addr, uint32_t* r) {
    asm volatile("ldmatrix.sync.aligned.m8n8.x4.shared.b16 {%0,%1,%2,%3}, [%4];"
                 : "=r"(r[0]), "=r"(r[1]), "=r"(r[2]), "=r"(r[3]) : "r"(addr));
}
__device__ __forceinline__ void mma16816(float* d, const uint32_t* a, uint32_t b0, uint32_t b1) {
    asm volatile(
        "mma.sync.aligned.m16n8k16.row.col.f32.bf16.bf16.f32 "
        "{%0,%1,%2,%3}, {%4,%5,%6,%7}, {%8,%9}, {%0,%1,%2,%3};"
        : "+f"(d[0]), "+f"(d[1]), "+f"(d[2]), "+f"(d[3])
        : "r"(a[0]), "r"(a[1]), "r"(a[2]), "r"(a[3]), "r"(b0), "r"(b1));
}

__global__ void __launch_bounds__(128) k_gemm_mma() {
    extern __shared__ char smem[];
    uint32_t sb = smem_u32(smem);
    int tid = threadIdx.x, wid = tid >> 5, lane = tid & 31;
    int m0 = blockIdx.x * 64;
    int valid = N_NODES - m0; if (valid > 64) valid = 64;

    // stage A hi/lo (64 x 128 bf16 each; 16 uint4 per row)
    {
        const uint4* gh = (const uint4*)(g_Ahi + (long long)m0 * DIM);
        const uint4* gl = (const uint4*)(g_Alo + (long long)m0 * DIM);
        #pragma unroll
        for (int i = tid; i < 1024; i += 128) {
            int r = i >> 4, c = i & 15;
            uint4 vh = make_uint4(0, 0, 0, 0), vl = make_uint4(0, 0, 0, 0);
            if (r < valid) { vh = gh[r * 16 + c]; vl = gl[r * 16 + c]; }
            *(uint4*)(smem + SM_AH + r * SAS + c * 16) = vh;
            *(uint4*)(smem + SM_AL + r * SAS + c * 16) = vl;
        }
        const uint4* wh = (const uint4*)g_Whi;
        const uint4* wl = (const uint4*)g_Wlo;
        #pragma unroll
        for (int i = tid; i < 2048; i += 128) {
            int r = i >> 4, c = i & 15;
            *(uint4*)(smem + SM_WH + r * SAS + c * 16) = wh[i];
            *(uint4*)(smem + SM_WL + r * SAS + c * 16) = wl[i];
        }
    }
    __syncthreads();

    float acc[16][4];
    #pragma unroll
    for (int j = 0; j < 16; j++)
        #pragma unroll
        for (int q = 0; q < 4; q++) acc[j][q] = 0.f;

    int wm = wid * 16;
    // A fragment address (per k-step): row = wm + (lane&15), col = kk*16 + (lane>>4)*8
    uint32_t a_off = (uint32_t)((wm + (lane & 15)) * SAS + ((lane >> 4) << 3) * 2);
    // B fragment address: row = nt*16 + (lane&7) + ((lane>>4)<<3), col = kk*16 + ((lane>>3)&1)*8
    uint32_t b_off = (uint32_t)(((lane & 7) + ((lane >> 4) << 3)) * SAS + (((lane >> 3) & 1) << 3) * 2);

    for (int kk = 0; kk < 8; kk++) {
        uint32_t kb = kk * 32;  // kk*16 elems * 2B
        uint32_t ah[4], al[4];
        ldsm4(sb + SM_AH + a_off + kb, ah);
        ldsm4(sb + SM_AL + a_off + kb, al);
        #pragma unroll
        for (int nt = 0; nt < 8; nt++) {
            uint32_t bh[4], bl[4];
            uint32_t nrow = nt * 16 * SAS;
            ldsm4(sb + SM_WH + nrow + b_off + kb, bh);
            ldsm4(sb + SM_WL + nrow + b_off + kb, bl);
            mma16816(acc[2 * nt],     ah, bh[0], bh[1]);
            mma16816(acc[2 * nt + 1], ah, bh[2], bh[3]);
            mma16816(acc[2 * nt],     ah, bl[0], bl[1]);
            mma16816(acc[2 * nt + 1], ah, bl[2], bl[3]);
            mma16816(acc[2 * nt],     al, bh[0], bh[1]);
            mma16816(acc[2 * nt + 1], al, bh[2], bh[3]);
        }
    }

    // epilogue: thread holds rows (wm + lane/4) and (+8), col pairs (lane%4)*2 per n8 tile
    int r0 = m0 + wm + (lane >> 2);
    int cb = (lane & 3) * 2;
    if (r0 < N_NODES) {
        float* d = g_hw + (long long)r0 * DIM;
        #pragma unroll
        for (int j = 0; j < 16; j++)
            *(float2*)(d + j * 8 + cb) = make_float2(acc[j][0], acc[j][1]);
    }
    if (r0 + 8 < N_NODES) {
        float* d = g_hw + (long long)(r0 + 8) * DIM;
        #pragma unroll
        for (int j = 0; j < 16; j++)
            *(float2*)(d + j * 8 + cb) = make_float2(acc[j][2], acc[j][3]);
    }
}

// ---------------- SpMM: fp32 gather, fp32 accumulate, relu, bf16-split out --------
__device__ __forceinline__ float4 f4fma(float s, float4 v, float4 a) {
    a.x += s * v.x; a.y += s * v.y; a.z += s * v.z; a.w += s * v.w; return a;
}

__global__ void __launch_bounds__(256) k_spmm(const float* __restrict__ bias) {
    int warp = (blockIdx.x * blockDim.x + threadIdx.x) >> 5;
    int lane = threadIdx.x & 31;
    if (warp >= N_NODES) return;
    int i = warp;

    const float4* hw4 = (const float4*)g_hw;
    float di = g_dinv[i];
    float sl = di * di;
    float4 acc = hw4[(long long)i * 32 + lane];
    acc.x *= sl; acc.y *= sl; acc.z *= sl; acc.w *= sl;

    int p = g_off[i], pe = g_off[i + 1];
    for (; p + 4 <= pe; p += 4) {
        int   s0 = g_csrc[p],     s1 = g_csrc[p + 1];
        int   s2 = g_csrc[p + 2], s3 = g_csrc[p + 3];
        float n0 = g_cnrm[p],     n1 = g_cnrm[p + 1];
        float n2 = g_cnrm[p + 2], n3 = g_cnrm[p + 3];
        float4 v0 = hw4[(long long)s0 * 32 + lane];
        float4 v1 = hw4[(long long)s1 * 32 + lane];
        float4 v2 = hw4[(long long)s2 * 32 + lane];
        float4 v3 = hw4[(long long)s3 * 32 + lane];
        acc = f4fma(n0, v0, acc);
        acc = f4fma(n1, v1, acc);
        acc = f4fma(n2, v2, acc);
        acc = f4fma(n3, v3, acc);
    }
    for (; p < pe; p++) {
        int s = g_csrc[p];
        acc = f4fma(g_cnrm[p], hw4[(long long)s * 32 + lane], acc);
    }

    float4 bv = ((const float4*)bias)[lane];
    acc.x = fmaxf(acc.x + bv.x, 0.f);
    acc.y = fmaxf(acc.y + bv.y, 0.f);
    acc.z = fmaxf(acc.z + bv.z, 0.f);
    acc.w = fmaxf(acc.w + bv.w, 0.f);

    // bf16 split store for next layer's GEMM
    uint2 ph, pl;
    ph.x = packbf2(acc.x, acc.y); ph.y = packbf2(acc.z, acc.w);
    __nv_bfloat162 t0 = *reinterpret_cast<__nv_bfloat162*>(&ph.x);
    __nv_bfloat162 t1 = *reinterpret_cast<__nv_bfloat162*>(&ph.y);
    pl.x = packbf2(acc.x - __bfloat162float(t0.x), acc.y - __bfloat162float(t0.y));
    pl.y = packbf2(acc.z - __bfloat162float(t1.x), acc.w - __bfloat162float(t1.y));
    ((uint2*)g_Ahi)[(long long)i * 32 + lane] = ph;
    ((uint2*)g_Alo)[(long long)i * 32 + lane] = pl;
}

// ---------------- global mean pool (batch is sorted) ----------------
__device__ __forceinline__ int lbound(const void* __restrict__ b, int key) {
    int lo = 0, hi = N_NODES;
    while (lo < hi) {
        int mid = (lo + hi) >> 1;
        if (ldidx(b, mid) < key) lo = mid + 1; else hi = mid;
    }
    return lo;
}
__global__ void k_zero_out(float* __restrict__ out) {
    int i = blockIdx.x * blockDim.x + threadIdx.x;
    if (i < NGRAPH * DIM) out[i] = 0.f;
}
#define PCH 16
__global__ void k_pool(const void* __restrict__ batch, float* __restrict__ out) {
    int g = blockIdx.x / PCH;
    int c = blockIdx.x % PCH;
    int t = threadIdx.x;
    int start = lbound(batch, g);
    int end   = lbound(batch, g + 1);
    int len = end - start;
    int rs = start + (int)((long long)len * c / PCH);
    int re = start + (int)((long long)len * (c + 1) / PCH);
    float s = 0.f;
    for (int r = rs; r < re; r++) {
        long long idx = (long long)r * DIM + t;
        s += __bfloat162float(g_Ahi[idx]) + __bfloat162float(g_Alo[idx]);
    }
    atomicAdd(&out[g * DIM + t], s);
}
__global__ void k_pool_div(const void* __restrict__ batch, float* __restrict__ out) {
    int g = blockIdx.x;
    int t = threadIdx.x;
    int start = lbound(batch, g);
    int end   = lbound(batch, g + 1);
    float cnt = (float)(end - start);
    if (cnt < 1.f) cnt = 1.f;
    out[g * DIM + t] /= cnt;
}

// ---------------- launch ----------------
extern "C" void kernel_launch(void* const* d_in, const int* in_sizes, int n_in,
                              void* d_out, int out_size) {
    (void)out_size;
    const float* x = 0; const void* ei = 0; const void* batch = 0;
    const float* W[3] = {0, 0, 0}; const float* b[3] = {0, 0, 0};
    int nw = 0, nb = 0;
    for (int i = 0; i < n_in; i++) {
        int sz = in_sizes[i];
        if      (sz == N_NODES * DIM) x     = (const float*)d_in[i];
        else if (sz == 2 * N_EDGES)   ei    = d_in[i];
        else if (sz == N_NODES)       batch = d_in[i];
        else if (sz == DIM * DIM)     { if (nw < 3) W[nw++] = (const float*)d_in[i]; }
        else if (sz == DIM)           { if (nb < 3) b[nb++] = (const float*)d_in[i]; }
    }
    float* out = (float*)d_out;

    cudaFuncSetAttribute(k_gemm_mma, cudaFuncAttributeMaxDynamicSharedMemorySize, SM_TOT);

    const int NT = 256;
    int nblk = (N_NODES + NT - 1) / NT;
    int eblk = (N_EDGES + NT - 1) / NT;
    int spmm_blocks = (N_NODES * 32 + NT - 1) / NT;
    int gemm_blocks = (N_NODES + 63) / 64;  // 782

    // preprocess
    k_detect<<<1, 256>>>((const int*)ei);
    k_init<<<nblk, NT>>>();
    k_degree<<<eblk, NT>>>(ei);
    k_dinv<<<nblk, NT>>>();
    k_scan<<<1, 1024>>>();
    k_fill<<<eblk, NT>>>(ei);

    // x -> bf16 split
    k_splitX<<<(N_NODES * DIM / 4 + NT - 1) / NT, NT>>>(x);

    for (int L = 0; L < 3; L++) {
        k_prepW<<<(DIM * DIM + NT - 1) / NT, NT>>>(W[L]);
        k_gemm_mma<<<gemm_blocks, 128, SM_TOT>>>();
        k_spmm<<<spmm_blocks, NT>>>(b[L]);
    }

    k_zero_out<<<(NGRAPH * DIM + NT - 1) / NT, NT>>>(out);
    k_pool<<<NGRAPH * PCH, DIM>>>(batch, out);
    k_pool_div<<<NGRAPH, DIM>>>(batch, out);
}

// round 5
// speedup vs baseline: 1.6828x; 1.1222x over previous
#include <cuda_runtime.h>
#include <cuda_bf16.h>
#include <cuda_fp16.h>
#include <cstdint>

#define N_NODES 50000
#define N_EDGES 800000
#define DIM     128
#define NGRAPH  64

// ---------------- scratch (static device globals; no allocation) ----------------
__device__ __nv_bfloat16 g_Ahi[N_NODES * DIM];   // GEMM input hi
__device__ __nv_bfloat16 g_Alo[N_NODES * DIM];   // GEMM input lo
__device__ __half        g_hw [N_NODES * DIM];   // GEMM output (SpMM gather input, fp16)
__device__ __nv_bfloat16 g_Whi[3 * DIM * DIM];   // W^T hi  [layer][n][k]
__device__ __nv_bfloat16 g_Wlo[3 * DIM * DIM];   // W^T lo  [layer][n][k]
__device__ int   g_deg[N_NODES];
__device__ float g_dinv[N_NODES];
__device__ int   g_off[N_NODES + 1];
__device__ int   g_cur[N_NODES];
__device__ int   g_csrc[N_EDGES];
__device__ float g_cnrm[N_EDGES];
__device__ int   g_is64;

// ---------------- small helpers ----------------
__device__ __forceinline__ int ldidx(const void* __restrict__ p, long long i) {
    if (g_is64) return (int)((const long long*)p)[i];
    return ((const int*)p)[i];
}
__device__ __forceinline__ uint32_t smem_u32(const void* p) {
    uint32_t a;
    asm("{ .reg .u64 t; cvta.to.shared.u64 t, %1; cvt.u32.u64 %0, t; }" : "=r"(a) : "l"(p));
    return a;
}
__device__ __forceinline__ uint32_t packbf2(float a, float b) {
    __nv_bfloat162 t = __floats2bfloat162_rn(a, b);
    return *reinterpret_cast<uint32_t*>(&t);
}
__device__ __forceinline__ float2 h2f2(uint32_t u) {
    __half2 h = *reinterpret_cast<__half2*>(&u);
    return __half22float2(h);
}

// ---------------- dtype detection (int32 vs int64 indices) ----------------
__global__ void k_detect(const int* __restrict__ probe) {
    __shared__ int nz;
    if (threadIdx.x == 0) nz = 0;
    __syncthreads();
    if (probe[threadIdx.x * 2 + 1] != 0) atomicAdd(&nz, 1);
    __syncthreads();
    if (threadIdx.x == 0) g_is64 = (nz == 0) ? 1 : 0;
}

// ---------------- preprocessing: CSR by dst ----------------
__global__ void k_init() {
    int i = blockIdx.x * blockDim.x + threadIdx.x;
    if (i < N_NODES) { g_deg[i] = 0; g_cur[i] = 0; }
}
__global__ void k_degree(const void* __restrict__ ei) {
    int e = blockIdx.x * blockDim.x + threadIdx.x;
    if (e < N_EDGES) atomicAdd(&g_deg[ldidx(ei, N_EDGES + e)], 1);
}
__global__ void k_dinv() {
    int i = blockIdx.x * blockDim.x + threadIdx.x;
    if (i < N_NODES) g_dinv[i] = rsqrtf((float)(g_deg[i] + 1));
}
__global__ void k_scan() {
    __shared__ int part[1024];
    const int CH = (N_NODES + 1023) / 1024;
    int t = threadIdx.x;
    int b = t * CH;
    int e = b + CH; if (e > N_NODES) e = N_NODES;
    int s = 0;
    for (int i = b; i < e; i++) s += g_deg[i];
    part[t] = s;
    __syncthreads();
    for (int d = 1; d < 1024; d <<= 1) {
        int v = (t >= d) ? part[t - d] : 0;
        __syncthreads();
        part[t] += v;
        __syncthreads();
    }
    int run = (t > 0) ? part[t - 1] : 0;
    for (int i = b; i < e; i++) { g_off[i] = run; run += g_deg[i]; }
    if (t == 1023) g_off[N_NODES] = part[1023];
}
__global__ void k_fill(const void* __restrict__ ei) {
    int e = blockIdx.x * blockDim.x + threadIdx.x;
    if (e >= N_EDGES) return;
    int s = ldidx(ei, e);
    int d = ldidx(ei, N_EDGES + e);
    int p = g_off[d] + atomicAdd(&g_cur[d], 1);
    g_csrc[p] = s;
    g_cnrm[p] = g_dinv[s] * g_dinv[d];
}

// ---------------- input conversion ----------------
__global__ void k_splitX(const float* __restrict__ x) {
    int i = blockIdx.x * blockDim.x + threadIdx.x;   // one float4 per thread
    if (i >= N_NODES * DIM / 4) return;
    float4 v = ((const float4*)x)[i];
    uint2 ph, pl;
    ph.x = packbf2(v.x, v.y); ph.y = packbf2(v.z, v.w);
    __nv_bfloat162 t0 = *reinterpret_cast<__nv_bfloat162*>(&ph.x);
    __nv_bfloat162 t1 = *reinterpret_cast<__nv_bfloat162*>(&ph.y);
    pl.x = packbf2(v.x - __bfloat162float(t0.x), v.y - __bfloat162float(t0.y));
    pl.y = packbf2(v.z - __bfloat162float(t1.x), v.w - __bfloat162float(t1.y));
    ((uint2*)g_Ahi)[i] = ph;
    ((uint2*)g_Alo)[i] = pl;
}

// W [k][n] fp32 -> W^T [n][k] (hi, lo) bf16, all three layers in one launch
__global__ void k_prepW3(const float* __restrict__ W0, const float* __restrict__ W1,
                         const float* __restrict__ W2) {
    int gidx = blockIdx.x * blockDim.x + threadIdx.x;
    if (gidx >= 3 * DIM * DIM) return;
    int L = gidx >> 14;
    int idx = gidx & (DIM * DIM - 1);
    const float* W = (L == 0) ? W0 : (L == 1) ? W1 : W2;
    int k = idx >> 7, n = idx & 127;
    float v = W[idx];
    __nv_bfloat16 hi = __float2bfloat16_rn(v);
    float lo = v - __bfloat162float(hi);
    g_Whi[L * DIM * DIM + n * DIM + k] = hi;
    g_Wlo[L * DIM * DIM + n * DIM + k] = __float2bfloat16_rn(lo);
}

// ---------------- mma.sync GEMM: g_hw[m][n] = sum_k A[m][k] * W[k][n] ----------------
// bf16 split x split (3 products), fp32 register accumulators, fp16 output.
// Block: 128 threads (4 warps), tile M=64, N=128, K=128.
#define SAS 272                 // smem row stride in BYTES (136 bf16)
#define SM_AH 0
#define SM_AL (SM_AH + 64 * SAS)
#define SM_WH (SM_AL + 64 * SAS)
#define SM_WL (SM_WH + 128 * SAS)
#define SM_TOT (SM_WL + 128 * SAS)

__device__ __forceinline__ void ldsm4(uint32_t addr, uint32_t* r) {
    asm volatile("ldmatrix.sync.aligned.m8n8.x4.shared.b16 {%0,%1,%2,%3}, [%4];"
                 : "=r"(r[0]), "=r"(r[1]), "=r"(r[2]), "=r"(r[3]) : "r"(addr));
}
__device__ __forceinline__ void mma16816(float* d, const uint32_t* a, uint32_t b0, uint32_t b1) {
    asm volatile(
        "mma.sync.aligned.m16n8k16.row.col.f32.bf16.bf16.f32 "
        "{%0,%1,%2,%3}, {%4,%5,%6,%7}, {%8,%9}, {%0,%1,%2,%3};"
        : "+f"(d[0]), "+f"(d[1]), "+f"(d[2]), "+f"(d[3])
        : "r"(a[0]), "r"(a[1]), "r"(a[2]), "r"(a[3]), "r"(b0), "r"(b1));
}

__global__ void __launch_bounds__(128) k_gemm_mma(int layer) {
    extern __shared__ char smem[];
    uint32_t sb = smem_u32(smem);
    int tid = threadIdx.x, wid = tid >> 5, lane = tid & 31;
    int m0 = blockIdx.x * 64;
    int valid = N_NODES - m0; if (valid > 64) valid = 64;

    // stage A hi/lo (64 x 128 bf16 each; 16 uint4 per row)
    {
        const uint4* gh = (const uint4*)(g_Ahi + (long long)m0 * DIM);
        const uint4* gl = (const uint4*)(g_Alo + (long long)m0 * DIM);
        #pragma unroll
        for (int i = tid; i < 1024; i += 128) {
            int r = i >> 4, c = i & 15;
            uint4 vh = make_uint4(0, 0, 0, 0), vl = make_uint4(0, 0, 0, 0);
            if (r < valid) { vh = gh[r * 16 + c]; vl = gl[r * 16 + c]; }
            *(uint4*)(smem + SM_AH + r * SAS + c * 16) = vh;
            *(uint4*)(smem + SM_AL + r * SAS + c * 16) = vl;
        }
        const uint4* wh = (const uint4*)(g_Whi + layer * DIM * DIM);
        const uint4* wl = (const uint4*)(g_Wlo + layer * DIM * DIM);
        #pragma unroll
        for (int i = tid; i < 2048; i += 128) {
            int r = i >> 4, c = i & 15;
            *(uint4*)(smem + SM_WH + r * SAS + c * 16) = wh[i];
            *(uint4*)(smem + SM_WL + r * SAS + c * 16) = wl[i];
        }
    }
    __syncthreads();

    float acc[16][4];
    #pragma unroll
    for (int j = 0; j < 16; j++)
        #pragma unroll
        for (int q = 0; q < 4; q++) acc[j][q] = 0.f;

    int wm = wid * 16;
    uint32_t a_off = (uint32_t)((wm + (lane & 15)) * SAS + ((lane >> 4) << 3) * 2);
    uint32_t b_off = (uint32_t)(((lane & 7) + ((lane >> 4) << 3)) * SAS + (((lane >> 3) & 1) << 3) * 2);

    for (int kk = 0; kk < 8; kk++) {
        uint32_t kb = kk * 32;
        uint32_t ah[4], al[4];
        ldsm4(sb + SM_AH + a_off + kb, ah);
        ldsm4(sb + SM_AL + a_off + kb, al);
        #pragma unroll
        for (int nt = 0; nt < 8; nt++) {
            uint32_t bh[4], bl[4];
            uint32_t nrow = nt * 16 * SAS;
            ldsm4(sb + SM_WH + nrow + b_off + kb, bh);
            ldsm4(sb + SM_WL + nrow + b_off + kb, bl);
            mma16816(acc[2 * nt],     ah, bh[0], bh[1]);
            mma16816(acc[2 * nt + 1], ah, bh[2], bh[3]);
            mma16816(acc[2 * nt],     ah, bl[0], bl[1]);
            mma16816(acc[2 * nt + 1], ah, bl[2], bl[3]);
            mma16816(acc[2 * nt],     al, bh[0], bh[1]);
            mma16816(acc[2 * nt + 1], al, bh[2], bh[3]);
        }
    }

    // epilogue: fp16 output. thread holds rows (wm + lane/4), (+8); col pair (lane%4)*2 per n8 tile
    int r0 = m0 + wm + (lane >> 2);
    int cb = (lane & 3) * 2;
    if (r0 < N_NODES) {
        __half* d = g_hw + (long long)r0 * DIM;
        #pragma unroll
        for (int j = 0; j < 16; j++) {
            __half2 h = __floats2half2_rn(acc[j][0], acc[j][1]);
            *(__half2*)(d + j * 8 + cb) = h;
        }
    }
    if (r0 + 8 < N_NODES) {
        __half* d = g_hw + (long long)(r0 + 8) * DIM;
        #pragma unroll
        for (int j = 0; j < 16; j++) {
            __half2 h = __floats2half2_rn(acc[j][2], acc[j][3]);
            *(__half2*)(d + j * 8 + cb) = h;
        }
    }
}

// ---------------- SpMM: fp16 gather, fp32 accumulate, relu, bf16-split out --------
__global__ void __launch_bounds__(256) k_spmm(const float* __restrict__ bias) {
    int warp = (blockIdx.x * blockDim.x + threadIdx.x) >> 5;
    int lane = threadIdx.x & 31;
    if (warp >= N_NODES) return;
    int i = warp;

    float di = g_dinv[i];
    float sl = di * di;
    float4 acc;
    {
        uint2 v = ((const uint2*)(g_hw + (long long)i * DIM))[lane];
        float2 a = h2f2(v.x), b = h2f2(v.y);
        acc = make_float4(sl * a.x, sl * a.y, sl * b.x, sl * b.y);
    }

    int p = g_off[i], pe = g_off[i + 1];
    for (; p + 4 <= pe; p += 4) {
        int   s0 = g_csrc[p],     s1 = g_csrc[p + 1];
        int   s2 = g_csrc[p + 2], s3 = g_csrc[p + 3];
        float n0 = g_cnrm[p],     n1 = g_cnrm[p + 1];
        float n2 = g_cnrm[p + 2], n3 = g_cnrm[p + 3];
        uint2 v0 = ((const uint2*)(g_hw + (long long)s0 * DIM))[lane];
        uint2 v1 = ((const uint2*)(g_hw + (long long)s1 * DIM))[lane];
        uint2 v2 = ((const uint2*)(g_hw + (long long)s2 * DIM))[lane];
        uint2 v3 = ((const uint2*)(g_hw + (long long)s3 * DIM))[lane];
        float2 a, b;
        a = h2f2(v0.x); b = h2f2(v0.y);
        acc.x += n0 * a.x; acc.y += n0 * a.y; acc.z += n0 * b.x; acc.w += n0 * b.y;
        a = h2f2(v1.x); b = h2f2(v1.y);
        acc.x += n1 * a.x; acc.y += n1 * a.y; acc.z += n1 * b.x; acc.w += n1 * b.y;
        a = h2f2(v2.x); b = h2f2(v2.y);
        acc.x += n2 * a.x; acc.y += n2 * a.y; acc.z += n2 * b.x; acc.w += n2 * b.y;
        a = h2f2(v3.x); b = h2f2(v3.y);
        acc.x += n3 * a.x; acc.y += n3 * a.y; acc.z += n3 * b.x; acc.w += n3 * b.y;
    }
    for (; p < pe; p++) {
        int s = g_csrc[p];
        float n = g_cnrm[p];
        uint2 v = ((const uint2*)(g_hw + (long long)s * DIM))[lane];
        float2 a = h2f2(v.x), b = h2f2(v.y);
        acc.x += n * a.x; acc.y += n * a.y; acc.z += n * b.x; acc.w += n * b.y;
    }

    float4 bv = ((const float4*)bias)[lane];
    acc.x = fmaxf(acc.x + bv.x, 0.f);
    acc.y = fmaxf(acc.y + bv.y, 0.f);
    acc.z = fmaxf(acc.z + bv.z, 0.f);
    acc.w = fmaxf(acc.w + bv.w, 0.f);

    // bf16 split store for next layer's GEMM
    uint2 ph, pl;
    ph.x = packbf2(acc.x, acc.y); ph.y = packbf2(acc.z, acc.w);
    __nv_bfloat162 t0 = *reinterpret_cast<__nv_bfloat162*>(&ph.x);
    __nv_bfloat162 t1 = *reinterpret_cast<__nv_bfloat162*>(&ph.y);
    pl.x = packbf2(acc.x - __bfloat162float(t0.x), acc.y - __bfloat162float(t0.y));
    pl.y = packbf2(acc.z - __bfloat162float(t1.x), acc.w - __bfloat162float(t1.y));
    ((uint2*)g_Ahi)[(long long)i * 32 + lane] = ph;
    ((uint2*)g_Alo)[(long long)i * 32 + lane] = pl;
}

// ---------------- global mean pool (batch is sorted) ----------------
__device__ __forceinline__ int lbound(const void* __restrict__ b, int key) {
    int lo = 0, hi = N_NODES;
    while (lo < hi) {
        int mid = (lo + hi) >> 1;
        if (ldidx(b, mid) < key) lo = mid + 1; else hi = mid;
    }
    return lo;
}
__global__ void k_zero_out(float* __restrict__ out) {
    int i = blockIdx.x * blockDim.x + threadIdx.x;
    if (i < NGRAPH * DIM) out[i] = 0.f;
}
#define PCH 16
__global__ void k_pool(const void* __restrict__ batch, float* __restrict__ out) {
    int g = blockIdx.x / PCH;
    int c = blockIdx.x % PCH;
    int t = threadIdx.x;
    int start = lbound(batch, g);
    int end   = lbound(batch, g + 1);
    int len = end - start;
    int rs = start + (int)((long long)len * c / PCH);
    int re = start + (int)((long long)len * (c + 1) / PCH);
    float s = 0.f;
    for (int r = rs; r < re; r++) {
        long long idx = (long long)r * DIM + t;
        s += __bfloat162float(g_Ahi[idx]) + __bfloat162float(g_Alo[idx]);
    }
    atomicAdd(&out[g * DIM + t], s);
}
__global__ void k_pool_div(const void* __restrict__ batch, float* __restrict__ out) {
    int g = blockIdx.x;
    int t = threadIdx.x;
    int start = lbound(batch, g);
    int end   = lbound(batch, g + 1);
    float cnt = (float)(end - start);
    if (cnt < 1.f) cnt = 1.f;
    out[g * DIM + t] /= cnt;
}

// ---------------- launch ----------------
extern "C" void kernel_launch(void* const* d_in, const int* in_sizes, int n_in,
                              void* d_out, int out_size) {
    (void)out_size;
    const float* x = 0; const void* ei = 0; const void* batch = 0;
    const float* W[3] = {0, 0, 0}; const float* b[3] = {0, 0, 0};
    int nw = 0, nb = 0;
    for (int i = 0; i < n_in; i++) {
        int sz = in_sizes[i];
        if      (sz == N_NODES * DIM) x     = (const float*)d_in[i];
        else if (sz == 2 * N_EDGES)   ei    = d_in[i];
        else if (sz == N_NODES)       batch = d_in[i];
        else if (sz == DIM * DIM)     { if (nw < 3) W[nw++] = (const float*)d_in[i]; }
        else if (sz == DIM)           { if (nb < 3) b[nb++] = (const float*)d_in[i]; }
    }
    float* out = (float*)d_out;

    cudaFuncSetAttribute(k_gemm_mma, cudaFuncAttributeMaxDynamicSharedMemorySize, SM_TOT);

    const int NT = 256;
    int nblk = (N_NODES + NT - 1) / NT;
    int eblk = (N_EDGES + NT - 1) / NT;
    int spmm_blocks = (N_NODES * 32 + NT - 1) / NT;
    int gemm_blocks = (N_NODES + 63) / 64;  // 782

    // preprocess
    k_detect<<<1, 256>>>((const int*)ei);
    k_init<<<nblk, NT>>>();
    k_degree<<<eblk, NT>>>(ei);
    k_dinv<<<nblk, NT>>>();
    k_scan<<<1, 1024>>>();
    k_fill<<<eblk, NT>>>(ei);

    // input conversions
    k_splitX<<<(N_NODES * DIM / 4 + NT - 1) / NT, NT>>>(x);
    k_prepW3<<<(3 * DIM * DIM + NT - 1) / NT, NT>>>(W[0], W[1], W[2]);

    for (int L = 0; L < 3; L++) {
        k_gemm_mma<<<gemm_blocks, 128, SM_TOT>>>(L);
        k_spmm<<<spmm_blocks, NT>>>(b[L]);
    }

    k_zero_out<<<(NGRAPH * DIM + NT - 1) / NT, NT>>>(out);
    k_pool<<<NGRAPH * PCH, DIM>>>(batch, out);
    k_pool_div<<<NGRAPH, DIM>>>(batch, out);
}